// round 1
// baseline (speedup 1.0000x reference)
#include <cuda_runtime.h>

// CTC loss forward algorithm.
// Shapes (fixed by problem): B=512, T=512, C=128, L=64, S=2L+1=129, blank=C-1=127.
// inputs: d_in[0] = y_true [B, L] int32 ; d_in[1] = y_pred [B, T, C] float32 (probs)
// output: d_out = loss [B, 1] float32

#define CTC_B 512
#define CTC_T 512
#define CTC_C 128
#define CTC_L 64
#define CTC_S 129          // 2*L + 1
#define CTC_BLANK 127

#define NTHREADS 160       // >= S (129), multiple of 32; threads 0..127 also handle row log

__device__ __forceinline__ float lae3(float x, float y, float z) {
    float m = fmaxf(x, fmaxf(y, z));
    float s = __expf(x - m) + __expf(y - m) + __expf(z - m);
    return m + __logf(s);
}

__global__ __launch_bounds__(NTHREADS) void ctc_kernel(
    const int* __restrict__ y_true,
    const float* __restrict__ y_pred,
    float* __restrict__ out)
{
    const float NEGV = -1e30f;
    const float EPS  = 1e-7f;

    const int b   = blockIdx.x;
    const int tid = threadIdx.x;

    // alpha double buffer with 2-element NEG pad in front (branch-free s-1, s-2)
    __shared__ float alphaBuf[2][CTC_S + 2];
    __shared__ float lpBuf[2][CTC_C];

    // ---- per-thread static state ----
    const int s = tid;                 // DP state index, valid if s < CTC_S
    int lab = CTC_BLANK;
    bool allow = false;
    if (s < CTC_S) {
        if (s & 1) {
            lab = y_true[b * CTC_L + (s >> 1)];
            if (s >= 2) {
                int prev = y_true[b * CTC_L + (s >> 1) - 1];
                allow = (lab != prev);
            }
        }
    }

    const float* rowbase = y_pred + (size_t)b * CTC_T * CTC_C;

    // row 0 log-probs
    if (tid < CTC_C) {
        lpBuf[0][tid] = __logf(rowbase[tid] + EPS);
    }
    if (tid < 2) {
        alphaBuf[0][tid] = NEGV;
        alphaBuf[1][tid] = NEGV;
    }
    __syncthreads();

    // alpha at t=0: only s=0 (blank) and s=1 (first label) reachable
    if (s < CTC_S) {
        float a0 = NEGV;
        if (s == 0) a0 = lpBuf[0][CTC_BLANK];
        else if (s == 1) a0 = lpBuf[0][lab];
        alphaBuf[0][s + 2] = a0;
    }
    // row 1 log-probs
    if (tid < CTC_C) {
        lpBuf[1][tid] = __logf(rowbase[CTC_C + tid] + EPS);
    }
    __syncthreads();

    // ---- main DP loop: one __syncthreads per time step ----
    // invariant at top of iter t: alpha_{t-1} in alphaBuf[(t-1)&1], logrow_t in lpBuf[t&1]
    for (int t = 1; t < CTC_T; ++t) {
        const int rp = t & 1;        // parity of row t / alpha_t
        const int pp = rp ^ 1;       // parity of alpha_{t-1} / row t+1 destination

        // prefetch next row early (overlaps with DP math below)
        float pf = 0.0f;
        const bool do_pref = (tid < CTC_C) && (t + 1 < CTC_T);
        if (do_pref) pf = rowbase[(size_t)(t + 1) * CTC_C + tid];

        if (s < CTC_S) {
            float x = alphaBuf[pp][s + 2];
            float y = alphaBuf[pp][s + 1];
            float z = allow ? alphaBuf[pp][s] : NEGV;
            float na = lae3(x, y, z) + lpBuf[rp][lab];
            alphaBuf[rp][s + 2] = na;
        }
        if (do_pref) lpBuf[pp][tid] = __logf(pf + EPS);

        __syncthreads();
    }

    // alpha_{T-1} lives in alphaBuf[(T-1)&1] = alphaBuf[1] (T=512)
    if (tid == 0) {
        float x = alphaBuf[(CTC_T - 1) & 1][CTC_S + 1];  // s = S-1
        float y = alphaBuf[(CTC_T - 1) & 1][CTC_S];      // s = S-2
        float m = fmaxf(x, y);
        float l = m + __logf(__expf(x - m) + __expf(y - m));
        out[b] = -l;
    }
}

extern "C" void kernel_launch(void* const* d_in, const int* in_sizes, int n_in,
                              void* d_out, int out_size) {
    const int*   y_true = (const int*)d_in[0];
    const float* y_pred = (const float*)d_in[1];
    float*       out    = (float*)d_out;
    (void)in_sizes; (void)n_in; (void)out_size;

    ctc_kernel<<<CTC_B, NTHREADS>>>(y_true, y_pred, out);
}

// round 3
// speedup vs baseline: 6.9846x; 6.9846x over previous
#include <cuda_runtime.h>
#include <cstdint>

// CTC loss, probability-domain forward algorithm with PER-LANE block-float
// exponents (fixes the R2 global-rescale dynamic-range failure).
// B=512, T=512, C=128, L=64, S=129, blank=127. One warp per batch element.
// Lane L owns states s=4L..4L+3 (a0..a3); lane 31 additionally owns s=128 (a4).
// Cross-lane dependency: alpha[4L-1] = lane L-1's a3, via one shfl_up,
// re-based into this lane's exponent frame by factor f = 2^(E_{L-1}-E_L).

#define CTC_B 512
#define CTC_T 512
#define CTC_C 128
#define CTC_L 64
#define PF 16              // load-pipeline depth (steps)
#define RS 8               // rescale period (steps)

__global__ __launch_bounds__(32) void ctc_kernel(
    const int* __restrict__ y_true,
    const float* __restrict__ y_pred,
    float* __restrict__ out)
{
    const float EPS = 1e-7f;
    const unsigned FULL = 0xffffffffu;
    const int b    = blockIdx.x;
    const int lane = threadIdx.x;

    // labels for odd states s=4L+1 (label 2L) and s=4L+3 (label 2L+1)
    const int* lrow = y_true + b * CTC_L;
    const int lab1 = lrow[2 * lane];
    const int lab3 = lrow[2 * lane + 1];
    const int prev1 = (lane > 0) ? lrow[2 * lane - 1] : -1;
    const bool allow1 = (lane > 0) && (lab1 != prev1);
    const bool allow3 = (lab3 != lab1);

    const float* base = y_pred + (size_t)b * CTC_T * CTC_C;
    const float* pbp = base + (CTC_C - 1);
    const float* p1p = base + lab1;
    const float* p3p = base + lab3;

    // PF-deep software pipeline of the 3 gathered probabilities per step
    float Pb[PF], P1[PF], P3[PF];
#pragma unroll
    for (int j = 0; j < PF; ++j) {
        Pb[j] = pbp[j * CTC_C];
        P1[j] = p1p[j * CTC_C];
        P3[j] = p3p[j * CTC_C];
    }

    // virtual pre-init: a0=1 on lane 0 makes step t=0 yield the reference init
    float a0 = (lane == 0) ? 1.0f : 0.0f;
    float a1 = 0.0f, a2 = 0.0f, a3 = 0.0f, a4 = 0.0f;
    int   E  = 0;            // per-lane accumulated exponent (alpha = a * 2^E)
    float f  = (lane == 0) ? 0.0f : 1.0f;   // neighbor re-basing factor

    for (int tb = 0; tb < CTC_T; tb += PF) {
#pragma unroll
        for (int j = 0; j < PF; ++j) {
            const int t = tb + j;
            const float pb = Pb[j] + EPS;
            const float p1 = P1[j] + EPS;
            const float p3 = P3[j] + EPS;
            if (t + PF < CTC_T) {                 // refill pipeline slot
                const int off = (t + PF) * CTC_C;
                Pb[j] = pbp[off];
                P1[j] = p1p[off];
                P3[j] = p3p[off];
            }
            // neighbor alpha[4L-1], re-based into my exponent frame
            const float am1 = __shfl_up_sync(FULL, a3, 1) * f;   // lane0: f=0 -> 0

            const float n0 = (a0 + am1) * pb;                         // s=4L   (blank)
            const float n1 = (a1 + a0 + (allow1 ? am1 : 0.0f)) * p1;  // s=4L+1
            const float n2 = (a2 + a1) * pb;                          // s=4L+2 (blank)
            const float n3 = (a3 + a2 + (allow3 ? a1 : 0.0f)) * p3;   // s=4L+3
            const float n4 = (a4 + a3) * pb;                          // s=128 (only lane31 meaningful)
            a0 = n0; a1 = n1; a2 = n2; a3 = n3; a4 = n4;

            if ((j & (RS - 1)) == (RS - 1)) {
                // ---- per-lane power-of-2 rescale ----
                float lm = fmaxf(fmaxf(a0, a1), fmaxf(a2, a3));
                lm = fmaxf(lm, a4);
                int e = (int)(__float_as_uint(lm) >> 23) - 127;
                const bool zero = (lm == 0.0f);
                if (zero) e = 0;
                const float sc = __uint_as_float((unsigned)(127 - e) << 23); // 2^-e exact
                a0 *= sc; a1 *= sc; a2 *= sc; a3 *= sc; a4 *= sc;
                E += e;
                // all-zero lanes (ahead of the DP wavefront) adopt neighbor's frame
                const int Ep = __shfl_up_sync(FULL, E, 1);
                if (zero && lane > 0) E = Ep;
                // neighbor re-basing factor for the next RS steps
                const int Ep2 = __shfl_up_sync(FULL, E, 1);
                int d = Ep2 - E;
                d = max(-126, min(126, d));
                f = __uint_as_float((unsigned)(127 + d) << 23);  // 2^d
                if (lane == 0) f = 0.0f;
            }
        }
    }

    if (lane == 31) {
        // P_total = alpha_{T-1}[S-1] + alpha_{T-1}[S-2] = (a4 + a3) * 2^E
        const float p = a4 + a3;
        out[b] = -(__logf(p) + (float)E * 0.69314718055994530942f);
    }
}

extern "C" void kernel_launch(void* const* d_in, const int* in_sizes, int n_in,
                              void* d_out, int out_size) {
    const int*   y_true = (const int*)d_in[0];
    const float* y_pred = (const float*)d_in[1];
    float*       outp   = (float*)d_out;
    (void)in_sizes; (void)n_in; (void)out_size;

    ctc_kernel<<<CTC_B, 32>>>(y_true, y_pred, outp);
}